// round 1
// baseline (speedup 1.0000x reference)
#include <cuda_runtime.h>

#define BATCH 2
#define SEQ   2048
#define DIM   1024
#define NH    16
#define HD    64
#define MROWS (BATCH*SEQ)   // 4096

// Scratch (allocation-free requirement): 4 x 16 MB
__device__ float g_q[MROWS * DIM];
__device__ float g_k[MROWS * DIM];
__device__ float g_v[MROWS * DIM];
__device__ float g_att[MROWS * DIM];

// ---------------------------------------------------------------------------
// C[M,N] = A[M,K] @ W[N,K]^T (+ bias). Row-major A and W (torch Linear).
// 128x128 block tile, 16 k-slice, 256 threads, 8x8 per-thread microtile.
// blockIdx.z selects among up to 3 (W, C) pairs (fused QKV projection).
// ---------------------------------------------------------------------------
template <bool BIAS>
__global__ __launch_bounds__(256) void gemm_nt(
    const float* __restrict__ A,
    const float* __restrict__ W0, const float* __restrict__ W1, const float* __restrict__ W2,
    const float* __restrict__ bias,
    float* __restrict__ C0, float* __restrict__ C1, float* __restrict__ C2,
    int K)
{
    const float* W = (blockIdx.z == 0) ? W0 : ((blockIdx.z == 1) ? W1 : W2);
    float*       C = (blockIdx.z == 0) ? C0 : ((blockIdx.z == 1) ? C1 : C2);

    // Padded stride 132 (mult of 4): aligned float4 compute loads, ~2-way store conflicts only.
    __shared__ float As[16][132];
    __shared__ float Bs[16][132];

    const int tid = threadIdx.x;
    const int tx  = tid & 15;       // micro col group
    const int ty  = tid >> 4;       // micro row group
    const int row0 = blockIdx.y * 128;
    const int col0 = blockIdx.x * 128;

    const int lrow = tid >> 2;      // 0..63 (loader row)
    const int lkv  = tid & 3;       // 0..3  (float4 within 16-wide k slice)

    float acc[8][8];
#pragma unroll
    for (int i = 0; i < 8; i++)
#pragma unroll
        for (int j = 0; j < 8; j++) acc[i][j] = 0.f;

    for (int k0 = 0; k0 < K; k0 += 16) {
#pragma unroll
        for (int ii = 0; ii < 2; ii++) {
            const int r = lrow + ii * 64;
            float4 av = *(const float4*)(A + (size_t)(row0 + r) * K + k0 + lkv * 4);
            float4 bv = *(const float4*)(W + (size_t)(col0 + r) * K + k0 + lkv * 4);
            As[lkv * 4 + 0][r] = av.x; As[lkv * 4 + 1][r] = av.y;
            As[lkv * 4 + 2][r] = av.z; As[lkv * 4 + 3][r] = av.w;
            Bs[lkv * 4 + 0][r] = bv.x; Bs[lkv * 4 + 1][r] = bv.y;
            Bs[lkv * 4 + 2][r] = bv.z; Bs[lkv * 4 + 3][r] = bv.w;
        }
        __syncthreads();

#pragma unroll
        for (int kk = 0; kk < 16; kk++) {
            float4 a0 = *(const float4*)&As[kk][ty * 8];
            float4 a1 = *(const float4*)&As[kk][ty * 8 + 4];
            float4 b0 = *(const float4*)&Bs[kk][tx * 8];
            float4 b1 = *(const float4*)&Bs[kk][tx * 8 + 4];
            float a[8] = {a0.x, a0.y, a0.z, a0.w, a1.x, a1.y, a1.z, a1.w};
            float b[8] = {b0.x, b0.y, b0.z, b0.w, b1.x, b1.y, b1.z, b1.w};
#pragma unroll
            for (int i = 0; i < 8; i++)
#pragma unroll
                for (int j = 0; j < 8; j++)
                    acc[i][j] += a[i] * b[j];
        }
        __syncthreads();
    }

#pragma unroll
    for (int i = 0; i < 8; i++) {
        const int r = row0 + ty * 8 + i;
#pragma unroll
        for (int j = 0; j < 8; j += 4) {
            const int c = col0 + tx * 8 + j;
            float4 v = make_float4(acc[i][j], acc[i][j + 1], acc[i][j + 2], acc[i][j + 3]);
            if (BIAS) {
                v.x += bias[c]; v.y += bias[c + 1]; v.z += bias[c + 2]; v.w += bias[c + 3];
            }
            *(float4*)(C + (size_t)r * DIM + c) = v;
        }
    }
}

// ---------------------------------------------------------------------------
// Flash attention, fp32. One thread = one query row (thread-private softmax
// state, no cross-thread reductions). Block = 128 query rows of one (b,h).
// K/V streamed through smem in 32x64 tiles (broadcast reads, conflict-free).
// ---------------------------------------------------------------------------
__global__ __launch_bounds__(128) void attn_kernel()
{
    __shared__ float Ks[32 * 64];
    __shared__ float Vs[32 * 64];

    const int t  = threadIdx.x;                 // 0..127
    const int bh = blockIdx.y;
    const int b  = bh >> 4;
    const int h  = bh & 15;
    const int qrow  = b * SEQ + blockIdx.x * 128 + t;
    const int krow0 = b * SEQ;

    const float scale = 0.125f;                 // hd^-0.5
    const float* qp = g_q + (size_t)qrow * DIM + h * HD;

    float4 q4[16];
#pragma unroll
    for (int c = 0; c < 16; c++) {
        float4 v = *(const float4*)(qp + c * 4);
        v.x *= scale; v.y *= scale; v.z *= scale; v.w *= scale;
        q4[c] = v;
    }

    float4 o4[16];
#pragma unroll
    for (int c = 0; c < 16; c++) o4[c] = make_float4(0.f, 0.f, 0.f, 0.f);
    float mcur = -1e30f;
    float lsum = 0.f;

    for (int j0 = 0; j0 < SEQ; j0 += 32) {
        // Cooperative load of K/V 32x64 tiles (coalesced 256B rows).
#pragma unroll
        for (int ii = 0; ii < 4; ii++) {
            const int f = ii * 128 + t;         // 0..511 float4 slots
            const int r = f >> 4;               // 0..31
            const int c = f & 15;               // 0..15
            const size_t goff = (size_t)(krow0 + j0 + r) * DIM + h * HD + c * 4;
            *(float4*)&Ks[r * 64 + c * 4] = *(const float4*)(g_k + goff);
            *(float4*)&Vs[r * 64 + c * 4] = *(const float4*)(g_v + goff);
        }
        __syncthreads();

        // Scores for 32 keys (fully unrolled so s[] stays in registers).
        float s[32];
#pragma unroll
        for (int j = 0; j < 32; j++) {
            const float4* kk = (const float4*)&Ks[j * 64];
            float a0 = 0.f, a1 = 0.f, a2 = 0.f, a3 = 0.f;
#pragma unroll
            for (int c = 0; c < 16; c++) {
                float4 kv = kk[c];
                a0 += q4[c].x * kv.x;
                a1 += q4[c].y * kv.y;
                a2 += q4[c].z * kv.z;
                a3 += q4[c].w * kv.w;
            }
            s[j] = (a0 + a1) + (a2 + a3);
        }

        // Online softmax update (thread-private).
        float bm = s[0];
#pragma unroll
        for (int j = 1; j < 32; j++) bm = fmaxf(bm, s[j]);
        const float mnew  = fmaxf(mcur, bm);
        const float alpha = __expf(mcur - mnew);
        float psum = 0.f;
#pragma unroll
        for (int j = 0; j < 32; j++) {
            s[j] = __expf(s[j] - mnew);
            psum += s[j];
        }
        lsum = lsum * alpha + psum;
#pragma unroll
        for (int c = 0; c < 16; c++) {
            o4[c].x *= alpha; o4[c].y *= alpha; o4[c].z *= alpha; o4[c].w *= alpha;
        }

        // o += p @ V
#pragma unroll
        for (int j = 0; j < 32; j++) {
            const float p = s[j];
            const float4* vv = (const float4*)&Vs[j * 64];
#pragma unroll
            for (int c = 0; c < 16; c++) {
                float4 v = vv[c];
                o4[c].x += p * v.x;
                o4[c].y += p * v.y;
                o4[c].z += p * v.z;
                o4[c].w += p * v.w;
            }
        }
        mcur = mnew;
        __syncthreads();
    }

    const float inv = 1.f / lsum;
    float* op = g_att + (size_t)qrow * DIM + h * HD;
#pragma unroll
    for (int c = 0; c < 16; c++) {
        float4 v = o4[c];
        v.x *= inv; v.y *= inv; v.z *= inv; v.w *= inv;
        *(float4*)(op + c * 4) = v;
    }
}

// ---------------------------------------------------------------------------
extern "C" void kernel_launch(void* const* d_in, const int* in_sizes, int n_in,
                              void* d_out, int out_size)
{
    const float* x  = (const float*)d_in[0];
    const float* wq = (const float*)d_in[1];
    const float* wk = (const float*)d_in[2];
    const float* wv = (const float*)d_in[3];
    const float* wo = (const float*)d_in[4];
    const float* bo = (const float*)d_in[5];
    float* out = (float*)d_out;

    float* q = nullptr; float* k = nullptr; float* v = nullptr; float* att = nullptr;
    cudaGetSymbolAddress((void**)&q,   g_q);
    cudaGetSymbolAddress((void**)&k,   g_k);
    cudaGetSymbolAddress((void**)&v,   g_v);
    cudaGetSymbolAddress((void**)&att, g_att);

    // Fused QKV projection: z in {0,1,2} selects (wq->q, wk->k, wv->v)
    {
        dim3 grid(DIM / 128, MROWS / 128, 3);
        gemm_nt<false><<<grid, 256>>>(x, wq, wk, wv, nullptr, q, k, v, DIM);
    }
    // Attention
    {
        dim3 grid(SEQ / 128, BATCH * NH);
        attn_kernel<<<grid, 128>>>();
    }
    // Output projection + bias
    {
        dim3 grid(DIM / 128, MROWS / 128, 1);
        gemm_nt<true><<<grid, 256>>>(att, wo, wo, wo, bo, out, out, out, DIM);
    }
}